// round 1
// baseline (speedup 1.0000x reference)
#include <cuda_runtime.h>
#include <cuda_bf16.h>

#define BB 2
#define H 256
#define W 832
#define NPIX (H*W)

#define TS 32
#define HALO 10
#define HW2 (TS + 2*HALO)   // 52
#define PMAX 352

// scratch (static device allocations are allowed)
__device__ float g_blur[2*BB*NPIX];   // z: 0..BB-1 = src batches, BB..2BB-1 = dst batches
__device__ float g_cs[2*BB*NPIX];
__device__ float g_ss[2*BB*NPIX];
__device__ float g_dxf[BB*NPIX];
__device__ float g_dyf[BB*NPIX];
__device__ float g_mk[BB*NPIX];

// ---------------- K1: circular 3x3 box blur of src and dst maps ----------------
__global__ void k_blur(const float* __restrict__ src, const float* __restrict__ dst) {
    int t = blockIdx.x * blockDim.x + threadIdx.x;
    if (t >= 2*BB*NPIX) return;
    int z = t / NPIX; int p = t - z*NPIX;
    int i = p / W, j = p - i*W;
    const float* m = (z < BB) ? (src + z*NPIX) : (dst + (z-BB)*NPIX);
    float s = 0.f;
#pragma unroll
    for (int a = -1; a <= 1; a++) {
        int ii = i + a; ii = (ii < 0) ? ii + H : ((ii >= H) ? ii - H : ii);
#pragma unroll
        for (int c = -1; c <= 1; c++) {
            int jj = j + c; jj = (jj < 0) ? jj + W : ((jj >= W) ? jj - W : jj);
            s += m[ii*W + jj];
        }
    }
    g_blur[t] = s;
}

// ---------------- K2: np.gradient + cos/sin of atan2(gy,gx) ----------------
__global__ void k_trig() {
    int t = blockIdx.x * blockDim.x + threadIdx.x;
    if (t >= 2*BB*NPIX) return;
    int z = t / NPIX; int p = t - z*NPIX;
    int i = p / W, j = p - i*W;
    const float* b = g_blur + z*NPIX;
    float gyv, gxv;
    if (i == 0)          gyv = b[W + j] - b[j];
    else if (i == H-1)   gyv = b[(H-1)*W + j] - b[(H-2)*W + j];
    else                 gyv = 0.5f * (b[(i+1)*W + j] - b[(i-1)*W + j]);
    if (j == 0)          gxv = b[i*W + 1] - b[i*W];
    else if (j == W-1)   gxv = b[i*W + W-1] - b[i*W + W-2];
    else                 gxv = 0.5f * (b[i*W + j+1] - b[i*W + j-1]);
    float r = sqrtf(gxv*gxv + gyv*gyv);
    float cs, ss;
    if (r > 0.f) { cs = gxv / r; ss = gyv / r; }
    else         { cs = 1.f;     ss = 0.f;     }   // atan2(0,0)=0
    g_cs[t] = cs; g_ss[t] = ss;
}

// ---------------- K3: sparsify (min-lin in 5x5) + windowed correspondence search ----------------
__global__ void k_search(const float* __restrict__ src, const float* __restrict__ dst,
                         const int* __restrict__ xx, const int* __restrict__ yy, int K) {
    int t = blockIdx.x * blockDim.x + threadIdx.x;
    if (t >= BB*NPIX) return;
    int bb = t / NPIX; int p = t - bb*NPIX;
    int i = p / W, j = p - i*W;
    const float* S = src + bb*NPIX;
    float dxo = 0.f, dyo = 0.f, mk = 0.f;
    if (S[p] > 0.5f) {
        // keep iff no edge with smaller linear index in 5x5 window
        bool kept = true;
        int mylin = p;
#pragma unroll
        for (int a = -2; a <= 2; a++) {
            int ii = i + a;
            if (ii < 0 || ii >= H) continue;
#pragma unroll
            for (int c = -2; c <= 2; c++) {
                int jj = j + c;
                if (jj < 0 || jj >= W) continue;
                int q = ii*W + jj;
                if (q < mylin && S[q] > 0.5f) kept = false;
            }
        }
        if (kept) {
            const float* D  = dst  + bb*NPIX;
            const float* cd = g_cs + (BB + bb)*NPIX;
            const float* sd = g_ss + (BB + bb)*NPIX;
            float cs = g_cs[bb*NPIX + p];
            float ssv = g_ss[bb*NPIX + p];
            float best = 1e9f; float bx = 0.f, by = 0.f;
            for (int k = 0; k < K; k++) {
                int ox = xx[k], oy = yy[k];
                int ii = i + oy, jj = j + ox;
                if (ii >= 0 && ii < H && jj >= 0 && jj < W) {
                    int q = ii*W + jj;
                    if (D[q] > 0.5f) {
                        float ang = 1.0f - (cs*cd[q] + ssv*sd[q]);
                        float sc = 20.0f * sqrtf((float)(ox*ox + oy*oy)) + 10.5f * ang;
                        if (sc < best) { best = sc; bx = (float)ox; by = (float)oy; }
                    }
                }
            }
            if (best < 5e8f) { dxo = bx; dyo = by; mk = 1.f; }
        }
    }
    g_dxf[t] = dxo; g_dyf[t] = dyo; g_mk[t] = mk;
}

// ---------------- K4: sparse diffusion over 21x21 sense window + final output ----------------
__global__ void __launch_bounds__(TS*TS) k_diffuse(float* __restrict__ out) {
    __shared__ float s_wk[441];
    __shared__ float s_dx[PMAX], s_dy[PMAX];
    __shared__ int   s_pos[PMAX];
    __shared__ int   s_wcnt[32], s_wbase[32];
    __shared__ int   s_total;

    int bb  = blockIdx.z;
    int ty0 = blockIdx.y * TS, tx0 = blockIdx.x * TS;
    int tid = threadIdx.y * TS + threadIdx.x;

    if (tid < 441) {
        int dy = tid / 21 - 10, dx = tid % 21 - 10;
        s_wk[tid] = expf(-sqrtf((float)(dx*dx + dy*dy)) / 5.0f);
    }

    const float* mk  = g_mk  + bb*NPIX;
    const float* gdx = g_dxf + bb*NPIX;
    const float* gdy = g_dyf + bb*NPIX;

    // deterministic compaction of active halo points into smem
    int base = 0;
    const int NCHUNK = (HW2*HW2 + TS*TS - 1) / (TS*TS);   // 3
#pragma unroll
    for (int chunk = 0; chunk < NCHUNK; chunk++) {
        int h = chunk * TS*TS + tid;
        bool act = false; float vx = 0.f, vy = 0.f; int pos = 0;
        if (h < HW2*HW2) {
            int hy = h / HW2, hx = h - hy*HW2;
            int gy = ty0 - HALO + hy, gx = tx0 - HALO + hx;
            if (gy >= 0 && gy < H && gx >= 0 && gx < W) {
                int q = gy*W + gx;
                if (mk[q] > 0.5f) { act = true; vx = gdx[q]; vy = gdy[q]; pos = (hy << 6) | hx; }
            }
        }
        unsigned bal = __ballot_sync(0xffffffffu, act);
        int wid = tid >> 5, lane = tid & 31;
        if (lane == 0) s_wcnt[wid] = __popc(bal);
        __syncthreads();
        if (tid == 0) {
            int run = base;
            for (int w2 = 0; w2 < 32; w2++) { s_wbase[w2] = run; run += s_wcnt[w2]; }
            s_total = run;
        }
        __syncthreads();
        if (act) {
            int idx = s_wbase[wid] + __popc(bal & ((1u << lane) - 1u));
            if (idx < PMAX) { s_dx[idx] = vx; s_dy[idx] = vy; s_pos[idx] = pos; }
        }
        base = s_total;
        __syncthreads();
    }
    int n = min(base, PMAX);

    int hy0 = threadIdx.y + HALO, hx0 = threadIdx.x + HALO;
    float nx = 0.f, ny = 0.f, den = 0.f;
    for (int pI = 0; pI < n; pI++) {
        int pos = s_pos[pI];
        int ddy = (pos >> 6) - hy0;
        int ddx = (pos & 63) - hx0;
        if (ddy >= -HALO && ddy <= HALO && ddx >= -HALO && ddx <= HALO) {
            float w = s_wk[(ddy + HALO) * 21 + (ddx + HALO)];
            nx += w * s_dx[pI];
            ny += w * s_dy[pI];
            den += w;
        }
    }
    float inv = 1.0f / (den + 1e-6f);
    int oy = ty0 + threadIdx.y, ox = tx0 + threadIdx.x;
    int q = oy*W + ox;
    out[(bb*2 + 0)*NPIX + q] = (float)ox + 0.6f * nx * inv;
    out[(bb*2 + 1)*NPIX + q] = (float)oy + 0.6f * ny * inv;
}

extern "C" void kernel_launch(void* const* d_in, const int* in_sizes, int n_in,
                              void* d_out, int out_size) {
    const float* src = (const float*)d_in[0];
    const float* dst = (const float*)d_in[1];
    const int*   xx  = (const int*)d_in[2];
    const int*   yy  = (const int*)d_in[3];
    int K = in_sizes[2];
    float* out = (float*)d_out;

    k_blur  <<<(2*BB*NPIX + 255)/256, 256>>>(src, dst);
    k_trig  <<<(2*BB*NPIX + 255)/256, 256>>>();
    k_search<<<(BB*NPIX + 255)/256, 256>>>(src, dst, xx, yy, K);
    dim3 g(W/TS, H/TS, BB), t(TS, TS);
    k_diffuse<<<g, t>>>(out);
}

// round 2
// speedup vs baseline: 1.1562x; 1.1562x over previous
#include <cuda_runtime.h>
#include <cuda_bf16.h>

#define BB 2
#define H 256
#define W 832
#define NPIX (H*W)

#define TS 32
#define HALO 10
#define HW2 (TS + 2*HALO)   // 52
#define PMAX 352            // >= 18*18 = 324 worst-case (kept points pairwise Chebyshev >= 3)
#define PTMAX 24576         // >= ceil(256/3)*ceil(832/3) = 23908 worst-case kept per batch

// scratch (static device allocations are allowed)
__device__ float g_cs[BB*NPIX], g_ss[BB*NPIX];     // dst orientation cos/sin
__device__ float g_dxf[BB*NPIX], g_dyf[BB*NPIX], g_mk[BB*NPIX];
__device__ int   g_cnt[BB];
__device__ int   g_ppos[BB*PTMAX];
__device__ float g_pcs[BB*PTMAX], g_pss[BB*PTMAX];

#define OTX 32
#define OTY 8

// ---------------- K1: fused circular 3x3 blur + gradient cos/sin + source sparsify ----------------
// z < BB : source plane  -> zero mk/dx/dy planes, detect kept edge points, push (pos, cs, ss)
// z >= BB: dest plane    -> write g_cs/g_ss
__global__ void __launch_bounds__(OTX*OTY) k_orient(const float* __restrict__ src,
                                                    const float* __restrict__ dst) {
    __shared__ float s_in[OTY+4][OTX+4];   // input tile, halo 2, circular wrap
    __shared__ float s_b[OTY+2][OTX+2];    // blurred tile, halo 1

    int z = blockIdx.z;
    int gy0 = blockIdx.y * OTY, gx0 = blockIdx.x * OTX;
    int tid = threadIdx.y * OTX + threadIdx.x;
    const float* m = (z < BB) ? (src + z*NPIX) : (dst + (z-BB)*NPIX);

    for (int h = tid; h < (OTY+4)*(OTX+4); h += OTY*OTX) {
        int r = h / (OTX+4), c = h - r*(OTX+4);
        int ii = gy0 - 2 + r; ii += (ii < 0) ? H : 0; ii -= (ii >= H) ? H : 0;
        int jj = gx0 - 2 + c; jj += (jj < 0) ? W : 0; jj -= (jj >= W) ? W : 0;
        s_in[r][c] = m[ii*W + jj];
    }
    __syncthreads();
    for (int h = tid; h < (OTY+2)*(OTX+2); h += OTY*OTX) {
        int r = h / (OTX+2), c = h - r*(OTX+2);
        float s = 0.f;
#pragma unroll
        for (int a = 0; a < 3; a++)
#pragma unroll
            for (int b2 = 0; b2 < 3; b2++) s += s_in[r+a][c+b2];
        s_b[r][c] = s;   // blurred at (gy0-1+r, gx0-1+c)
    }
    __syncthreads();

    int ty = threadIdx.y, tx = threadIdx.x;
    int i = gy0 + ty, j = gx0 + tx;
    int p = i*W + j;

    if (z >= BB) {
        // np.gradient on blurred map, edge-clamped one-sided
        float gyv, gxv;
        if (i == 0)        gyv = s_b[ty+2][tx+1] - s_b[ty+1][tx+1];
        else if (i == H-1) gyv = s_b[ty+1][tx+1] - s_b[ty  ][tx+1];
        else               gyv = 0.5f * (s_b[ty+2][tx+1] - s_b[ty][tx+1]);
        if (j == 0)        gxv = s_b[ty+1][tx+2] - s_b[ty+1][tx+1];
        else if (j == W-1) gxv = s_b[ty+1][tx+1] - s_b[ty+1][tx  ];
        else               gxv = 0.5f * (s_b[ty+1][tx+2] - s_b[ty+1][tx]);
        float r = sqrtf(gxv*gxv + gyv*gyv);
        float cs, ss;
        if (r > 0.f) { cs = gxv / r; ss = gyv / r; }
        else         { cs = 1.f;     ss = 0.f;     }
        int b = z - BB;
        g_cs[b*NPIX + p] = cs;
        g_ss[b*NPIX + p] = ss;
    } else {
        int b = z;
        g_mk[b*NPIX + p] = 0.f; g_dxf[b*NPIX + p] = 0.f; g_dyf[b*NPIX + p] = 0.f;
        if (s_in[ty+2][tx+2] > 0.5f) {
            bool kept = true;
#pragma unroll
            for (int a = -2; a <= 2; a++) {
                int ii = i + a;
                if (ii < 0 || ii >= H) continue;
#pragma unroll
                for (int c = -2; c <= 2; c++) {
                    int jj = j + c;
                    if (jj < 0 || jj >= W) continue;
                    if ((ii*W + jj) < p && s_in[ty+2+a][tx+2+c] > 0.5f) kept = false;
                }
            }
            if (kept) {
                float gyv, gxv;
                if (i == 0)        gyv = s_b[ty+2][tx+1] - s_b[ty+1][tx+1];
                else if (i == H-1) gyv = s_b[ty+1][tx+1] - s_b[ty  ][tx+1];
                else               gyv = 0.5f * (s_b[ty+2][tx+1] - s_b[ty][tx+1]);
                if (j == 0)        gxv = s_b[ty+1][tx+2] - s_b[ty+1][tx+1];
                else if (j == W-1) gxv = s_b[ty+1][tx+1] - s_b[ty+1][tx  ];
                else               gxv = 0.5f * (s_b[ty+1][tx+2] - s_b[ty+1][tx]);
                float r = sqrtf(gxv*gxv + gyv*gyv);
                float cs, ss;
                if (r > 0.f) { cs = gxv / r; ss = gyv / r; }
                else         { cs = 1.f;     ss = 0.f;     }
                int idx = atomicAdd(&g_cnt[b], 1);
                if (idx < PTMAX) {
                    g_ppos[b*PTMAX + idx] = p;
                    g_pcs [b*PTMAX + idx] = cs;
                    g_pss [b*PTMAX + idx] = ss;
                }
            }
        }
    }
}

// ---------------- K2: one warp per kept point, 105 offsets over lanes ----------------
__global__ void k_match(const float* __restrict__ dst,
                        const int* __restrict__ xx, const int* __restrict__ yy, int K) {
    int b = blockIdx.y;
    int lane = threadIdx.x & 31;
    int warp = (blockIdx.x * blockDim.x + threadIdx.x) >> 5;
    int nwarps = (gridDim.x * blockDim.x) >> 5;
    int cnt = min(g_cnt[b], PTMAX);
    const float* D  = dst  + b*NPIX;
    const float* cd = g_cs + b*NPIX;
    const float* sd = g_ss + b*NPIX;

    for (int pt = warp; pt < cnt; pt += nwarps) {
        int p = g_ppos[b*PTMAX + pt];
        float cs  = g_pcs[b*PTMAX + pt];
        float ssv = g_pss[b*PTMAX + pt];
        int i = p / W, j = p - (p / W) * W;
        float best = 1e9f; int bk = 0x7fffffff;
        for (int k = lane; k < K; k += 32) {
            int ox = xx[k], oy = yy[k];
            int ii = i + oy, jj = j + ox;
            if (ii >= 0 && ii < H && jj >= 0 && jj < W) {
                int q = ii*W + jj;
                if (D[q] > 0.5f) {
                    float ang = 1.0f - (cs*cd[q] + ssv*sd[q]);
                    float sc = 20.0f * sqrtf((float)(ox*ox + oy*oy)) + 10.5f * ang;
                    if (sc < best) { best = sc; bk = k; }   // ascending k: first-min within lane
                }
            }
        }
        // warp lexicographic (score, k) min -> global first-index-of-min
#pragma unroll
        for (int o = 16; o; o >>= 1) {
            float s2 = __shfl_xor_sync(0xffffffffu, best, o);
            int   k2 = __shfl_xor_sync(0xffffffffu, bk, o);
            if (s2 < best || (s2 == best && k2 < bk)) { best = s2; bk = k2; }
        }
        if (lane == 0 && best < 5e8f) {
            g_mk [b*NPIX + p] = 1.f;
            g_dxf[b*NPIX + p] = (float)xx[bk];
            g_dyf[b*NPIX + p] = (float)yy[bk];
        }
    }
}

// ---------------- K3: sparse diffusion over 21x21 sense window + final output ----------------
__global__ void __launch_bounds__(TS*TS) k_diffuse(float* __restrict__ out) {
    __shared__ float s_wk[441];
    __shared__ float s_dx[PMAX], s_dy[PMAX];
    __shared__ int   s_pos[PMAX];
    __shared__ int   s_wcnt[32], s_wbase[32];
    __shared__ int   s_total;

    int bb  = blockIdx.z;
    int ty0 = blockIdx.y * TS, tx0 = blockIdx.x * TS;
    int tid = threadIdx.y * TS + threadIdx.x;

    if (tid < 441) {
        int dy = tid / 21 - 10, dx = tid % 21 - 10;
        s_wk[tid] = expf(-sqrtf((float)(dx*dx + dy*dy)) / 5.0f);
    }

    const float* mk  = g_mk  + bb*NPIX;
    const float* gdx = g_dxf + bb*NPIX;
    const float* gdy = g_dyf + bb*NPIX;

    // deterministic raster-order compaction of active halo points -> s_pos ascending in hy
    int base = 0;
    const int NCHUNK = (HW2*HW2 + TS*TS - 1) / (TS*TS);   // 3
#pragma unroll
    for (int chunk = 0; chunk < NCHUNK; chunk++) {
        int h = chunk * TS*TS + tid;
        bool act = false; float vx = 0.f, vy = 0.f; int pos = 0;
        if (h < HW2*HW2) {
            int hy = h / HW2, hx = h - hy*HW2;
            int gy = ty0 - HALO + hy, gx = tx0 - HALO + hx;
            if (gy >= 0 && gy < H && gx >= 0 && gx < W) {
                int q = gy*W + gx;
                if (mk[q] > 0.5f) { act = true; vx = gdx[q]; vy = gdy[q]; pos = (hy << 6) | hx; }
            }
        }
        unsigned bal = __ballot_sync(0xffffffffu, act);
        int wid = tid >> 5, lane = tid & 31;
        if (lane == 0) s_wcnt[wid] = __popc(bal);
        __syncthreads();
        if (tid < 32) {
            int c = s_wcnt[tid], x = c;
#pragma unroll
            for (int o = 1; o < 32; o <<= 1) {
                int y = __shfl_up_sync(0xffffffffu, x, o);
                if (tid >= o) x += y;
            }
            s_wbase[tid] = base + x - c;
            if (tid == 31) s_total = base + x;
        }
        __syncthreads();
        if (act) {
            int idx = s_wbase[wid] + __popc(bal & ((1u << lane) - 1u));
            if (idx < PMAX) { s_dx[idx] = vx; s_dy[idx] = vy; s_pos[idx] = pos; }
        }
        base = s_total;
        __syncthreads();
    }
    int n = min(base, PMAX);

    // warp-uniform row band: this warp's pixels all have hy0 = threadIdx.y + HALO
    int hy0 = threadIdx.y + HALO, hx0 = threadIdx.x + HALO;
    int lokey = (hy0 - HALO) << 6;
    int hikey = ((hy0 + HALO) << 6) | 63;
    int lo, hi;
    { int a = 0, b2 = n; while (a < b2) { int m2 = (a + b2) >> 1; if (s_pos[m2] <  lokey) a = m2 + 1; else b2 = m2; } lo = a; }
    { int a = lo, b2 = n; while (a < b2) { int m2 = (a + b2) >> 1; if (s_pos[m2] <= hikey) a = m2 + 1; else b2 = m2; } hi = a; }

    float nx = 0.f, ny = 0.f, den = 0.f;
    for (int pI = lo; pI < hi; pI++) {
        int pos = s_pos[pI];
        int ddx = (pos & 63) - hx0;
        if (ddx >= -HALO && ddx <= HALO) {
            int ddy = (pos >> 6) - hy0;
            float w = s_wk[(ddy + HALO) * 21 + (ddx + HALO)];
            nx += w * s_dx[pI];
            ny += w * s_dy[pI];
            den += w;
        }
    }
    float inv = 1.0f / (den + 1e-6f);
    int oy = ty0 + threadIdx.y, ox = tx0 + threadIdx.x;
    int q = oy*W + ox;
    out[(bb*2 + 0)*NPIX + q] = (float)ox + 0.6f * nx * inv;
    out[(bb*2 + 1)*NPIX + q] = (float)oy + 0.6f * ny * inv;
}

extern "C" void kernel_launch(void* const* d_in, const int* in_sizes, int n_in,
                              void* d_out, int out_size) {
    const float* src = (const float*)d_in[0];
    const float* dst = (const float*)d_in[1];
    const int*   xx  = (const int*)d_in[2];
    const int*   yy  = (const int*)d_in[3];
    int K = in_sizes[2];
    float* out = (float*)d_out;

    void* cntp = nullptr;
    cudaGetSymbolAddress(&cntp, g_cnt);
    cudaMemsetAsync(cntp, 0, BB * sizeof(int));

    dim3 go(W/OTX, H/OTY, 2*BB), to(OTX, OTY);
    k_orient<<<go, to>>>(src, dst);

    dim3 gm(52, BB);
    k_match<<<gm, 256>>>(dst, xx, yy, K);

    dim3 gd(W/TS, H/TS, BB), td(TS, TS);
    k_diffuse<<<gd, td>>>(out);
}

// round 3
// speedup vs baseline: 1.6575x; 1.4337x over previous
#include <cuda_runtime.h>
#include <cuda_bf16.h>

#define BB 2
#define H 256
#define W 832
#define NPIX (H*W)

#define TS 32
#define HALO 10
#define PMAX 352            // >= 18*18 = 324 (kept points pairwise Chebyshev >= 3 in 52x52 halo)
#define PTMAX 24576         // >= ceil(256/3)*ceil(832/3) worst-case actives per batch

// compact active-point list (pos packed (i<<16)|j, displacement dx,dy)
__device__ int   g_acnt[BB];
__device__ int   g_apos[BB*PTMAX];
__device__ float g_adx[BB*PTMAX], g_ady[BB*PTMAX];

// on-demand orientation: circular 3x3 box blur + edge-clamped np.gradient -> (cos, sin) of atan2
__device__ __forceinline__ void orient(const float* __restrict__ m, int i, int j,
                                       float& cs, float& ss) {
    float patch[5][5];
#pragma unroll
    for (int r = 0; r < 5; r++) {
        int ii = i + r - 2; ii += (ii < 0) ? H : 0; ii -= (ii >= H) ? H : 0;
#pragma unroll
        for (int c = 0; c < 5; c++) {
            int jj = j + c - 2; jj += (jj < 0) ? W : 0; jj -= (jj >= W) ? W : 0;
            patch[r][c] = m[ii*W + jj];
        }
    }
#define BLUR_AT(di, dj) (patch[1+di][1+dj] + patch[1+di][2+dj] + patch[1+di][3+dj] \
                       + patch[2+di][1+dj] + patch[2+di][2+dj] + patch[2+di][3+dj] \
                       + patch[3+di][1+dj] + patch[3+di][2+dj] + patch[3+di][3+dj])
    float byp = BLUR_AT(1, 0), bym = BLUR_AT(-1, 0), bc = BLUR_AT(0, 0);
    float bxp = BLUR_AT(0, 1), bxm = BLUR_AT(0, -1);
#undef BLUR_AT
    float gyv = (i == 0) ? (byp - bc) : (i == H-1) ? (bc - bym) : 0.5f * (byp - bym);
    float gxv = (j == 0) ? (bxp - bc) : (j == W-1) ? (bc - bxm) : 0.5f * (bxp - bxm);
    float r = sqrtf(gxv*gxv + gyv*gyv);
    if (r > 0.f) { cs = gxv / r; ss = gyv / r; }
    else         { cs = 1.f;     ss = 0.f;     }   // atan2(0,0)=0
}

// ---------------- K1: fused sparsify + correspondence search ----------------
#define STY 8
#define STX 32
__global__ void __launch_bounds__(STY*STX) k_seed(const float* __restrict__ src,
                                                  const float* __restrict__ dst,
                                                  const int* __restrict__ xx,
                                                  const int* __restrict__ yy, int K) {
    __shared__ int s_pos[48];
    __shared__ int s_cnt;

    int b = blockIdx.z;
    int gy0 = blockIdx.y * STY, gx0 = blockIdx.x * STX;
    int tid = threadIdx.y * STX + threadIdx.x;
    const float* S = src + b*NPIX;
    const float* D = dst + b*NPIX;

    if (tid == 0) s_cnt = 0;
    __syncthreads();

    // phase 1: keep-test (min linear index edge in 5x5 window)
    int i = gy0 + threadIdx.y, j = gx0 + threadIdx.x;
    int p = i*W + j;
    if (S[p] > 0.5f) {
        bool kept = true;
#pragma unroll
        for (int a = -2; a <= 2; a++) {
            int ii = i + a;
            if (ii < 0 || ii >= H) continue;
#pragma unroll
            for (int c = -2; c <= 2; c++) {
                int jj = j + c;
                if (jj < 0 || jj >= W) continue;
                int q = ii*W + jj;
                if (q < p && S[q] > 0.5f) kept = false;
            }
        }
        if (kept) { int idx = atomicAdd(&s_cnt, 1); s_pos[idx] = p; }
    }
    __syncthreads();
    int n = s_cnt;

    // phase 2: warp per kept point, 105 offsets over lanes
    int warp = tid >> 5, lane = tid & 31;
    for (int pt = warp; pt < n; pt += STY*STX/32) {
        int pp = s_pos[pt];
        int pi = pp / W, pj = pp - (pp / W) * W;
        float cs, ssv;
        orient(S, pi, pj, cs, ssv);   // uniform addresses across warp -> broadcast loads
        float best = 1e9f; int bk = 0x7fffffff;
        for (int k = lane; k < K; k += 32) {
            int ox = xx[k], oy = yy[k];
            int ii = pi + oy, jj = pj + ox;
            if (ii >= 0 && ii < H && jj >= 0 && jj < W) {
                int q = ii*W + jj;
                if (D[q] > 0.5f) {
                    float cd, sd;
                    orient(D, ii, jj, cd, sd);   // rare (~2 hits/point)
                    float ang = 1.0f - (cs*cd + ssv*sd);
                    float sc = 20.0f * sqrtf((float)(ox*ox + oy*oy)) + 10.5f * ang;
                    if (sc < best) { best = sc; bk = k; }
                }
            }
        }
        // warp lexicographic (score, k) min -> global first-index-of-min (argmin semantics)
#pragma unroll
        for (int o = 16; o; o >>= 1) {
            float s2 = __shfl_xor_sync(0xffffffffu, best, o);
            int   k2 = __shfl_xor_sync(0xffffffffu, bk, o);
            if (s2 < best || (s2 == best && k2 < bk)) { best = s2; bk = k2; }
        }
        if (lane == 0 && best < 5e8f) {
            int idx = atomicAdd(&g_acnt[b], 1);
            if (idx < PTMAX) {
                g_apos[b*PTMAX + idx] = (pi << 16) | pj;
                g_adx [b*PTMAX + idx] = (float)xx[bk];
                g_ady [b*PTMAX + idx] = (float)yy[bk];
            }
        }
    }
}

// ---------------- K2: sparse diffusion over 21x21 sense window + final output ----------------
__global__ void __launch_bounds__(TS*TS) k_diffuse(float* __restrict__ out) {
    __shared__ float s_wk[441];
    __shared__ int   s_tp[PMAX];
    __shared__ float s_tdx[PMAX], s_tdy[PMAX];
    __shared__ int   s_pos[PMAX];
    __shared__ float s_dx[PMAX], s_dy[PMAX];
    __shared__ int   s_wcnt[32], s_wbase[32];
    __shared__ int   s_total;

    int bb  = blockIdx.z;
    int ty0 = blockIdx.y * TS, tx0 = blockIdx.x * TS;
    int tid = threadIdx.y * TS + threadIdx.x;

    if (tid < 441) {
        int dy = tid / 21 - 10, dx = tid % 21 - 10;
        s_wk[tid] = expf(-sqrtf((float)(dx*dx + dy*dy)) / 5.0f);
    }

    int cnt = min(g_acnt[bb], PTMAX);

    // cooperative bbox filter of the global active list -> unsorted smem list
    int base = 0;
    for (int h0 = 0; h0 < cnt; h0 += TS*TS) {
        int h = h0 + tid;
        bool act = false; int key = 0; float vx = 0.f, vy = 0.f;
        if (h < cnt) {
            int pos = g_apos[bb*PTMAX + h];
            int py = pos >> 16, px = pos & 0xffff;
            int ry = py - (ty0 - HALO), rx = px - (tx0 - HALO);
            if (ry >= 0 && ry < TS + 2*HALO && rx >= 0 && rx < TS + 2*HALO) {
                act = true; key = (ry << 6) | rx;
                vx = g_adx[bb*PTMAX + h]; vy = g_ady[bb*PTMAX + h];
            }
        }
        unsigned bal = __ballot_sync(0xffffffffu, act);
        int wid = tid >> 5, lane = tid & 31;
        if (lane == 0) s_wcnt[wid] = __popc(bal);
        __syncthreads();
        if (tid < 32) {
            int c = s_wcnt[tid], x = c;
#pragma unroll
            for (int o = 1; o < 32; o <<= 1) {
                int y = __shfl_up_sync(0xffffffffu, x, o);
                if (tid >= o) x += y;
            }
            s_wbase[tid] = base + x - c;
            if (tid == 31) s_total = base + x;
        }
        __syncthreads();
        if (act) {
            int idx = s_wbase[wid] + __popc(bal & ((1u << lane) - 1u));
            if (idx < PMAX) { s_tp[idx] = key; s_tdx[idx] = vx; s_tdy[idx] = vy; }
        }
        base = s_total;
        __syncthreads();
    }
    int m = min(base, PMAX);

    // rank sort (keys unique): ascending (ry,rx) for row-band binary search
    if (tid < m) {
        int my = s_tp[tid]; int r = 0;
        for (int q2 = 0; q2 < m; q2++) {
            int v = s_tp[q2];
            r += (v < my) ? 1 : 0;
        }
        s_pos[r] = my; s_dx[r] = s_tdx[tid]; s_dy[r] = s_tdy[tid];
    }
    __syncthreads();

    // warp-uniform row band: this warp's pixels all have hy0 = threadIdx.y + HALO
    int hy0 = threadIdx.y + HALO, hx0 = threadIdx.x + HALO;
    int lokey = threadIdx.y << 6;
    int hikey = ((threadIdx.y + 2*HALO) << 6) | 63;
    int lo, hi;
    { int a = 0, b2 = m; while (a < b2) { int m2 = (a + b2) >> 1; if (s_pos[m2] <  lokey) a = m2 + 1; else b2 = m2; } lo = a; }
    { int a = lo, b2 = m; while (a < b2) { int m2 = (a + b2) >> 1; if (s_pos[m2] <= hikey) a = m2 + 1; else b2 = m2; } hi = a; }

    float nx = 0.f, ny = 0.f, den = 0.f;
    for (int pI = lo; pI < hi; pI++) {
        int pos = s_pos[pI];
        int ddx = (pos & 63) - hx0;
        if (ddx >= -HALO && ddx <= HALO) {
            int ddy = (pos >> 6) - hy0;
            float w = s_wk[(ddy + HALO) * 21 + (ddx + HALO)];
            nx += w * s_dx[pI];
            ny += w * s_dy[pI];
            den += w;
        }
    }
    float inv = 1.0f / (den + 1e-6f);
    int oy = ty0 + threadIdx.y, ox = tx0 + threadIdx.x;
    int q = oy*W + ox;
    out[(bb*2 + 0)*NPIX + q] = (float)ox + 0.6f * nx * inv;
    out[(bb*2 + 1)*NPIX + q] = (float)oy + 0.6f * ny * inv;
}

extern "C" void kernel_launch(void* const* d_in, const int* in_sizes, int n_in,
                              void* d_out, int out_size) {
    const float* src = (const float*)d_in[0];
    const float* dst = (const float*)d_in[1];
    const int*   xx  = (const int*)d_in[2];
    const int*   yy  = (const int*)d_in[3];
    int K = in_sizes[2];
    float* out = (float*)d_out;

    void* cntp = nullptr;
    cudaGetSymbolAddress(&cntp, g_acnt);
    cudaMemsetAsync(cntp, 0, BB * sizeof(int));

    dim3 gs(W/STX, H/STY, BB), ts(STX, STY);
    k_seed<<<gs, ts>>>(src, dst, xx, yy, K);

    dim3 gd(W/TS, H/TS, BB), td(TS, TS);
    k_diffuse<<<gd, td>>>(out);
}

// round 4
// speedup vs baseline: 1.8356x; 1.1074x over previous
#include <cuda_runtime.h>
#include <cuda_bf16.h>

#define BB 2
#define H 256
#define W 832
#define NPIX (H*W)

#define TS 32
#define HALO 10
#define TY_N (H/TS)          // 8
#define TX_N (W/TS)          // 26
#define NTILE (TY_N*TX_N)    // 208 per batch
#define TCAP 352             // >= 18*18 = 324 (kept points pairwise Chebyshev >= 3 in 52x52 halo)

// per-tile binned active-point lists
__device__ int    g_tcnt[BB*NTILE];
__device__ int    g_tpos[BB*NTILE*TCAP];     // (i<<16)|j
__device__ float2 g_tdxy[BB*NTILE*TCAP];

// on-demand orientation: circular 3x3 box blur + edge-clamped np.gradient -> (cos, sin) of atan2
__device__ __forceinline__ void orient(const float* __restrict__ m, int i, int j,
                                       float& cs, float& ss) {
    float patch[5][5];
#pragma unroll
    for (int r = 0; r < 5; r++) {
        int ii = i + r - 2; ii += (ii < 0) ? H : 0; ii -= (ii >= H) ? H : 0;
#pragma unroll
        for (int c = 0; c < 5; c++) {
            int jj = j + c - 2; jj += (jj < 0) ? W : 0; jj -= (jj >= W) ? W : 0;
            patch[r][c] = m[ii*W + jj];
        }
    }
#define BLUR_AT(di, dj) (patch[1+di][1+dj] + patch[1+di][2+dj] + patch[1+di][3+dj] \
                       + patch[2+di][1+dj] + patch[2+di][2+dj] + patch[2+di][3+dj] \
                       + patch[3+di][1+dj] + patch[3+di][2+dj] + patch[3+di][3+dj])
    float byp = BLUR_AT(1, 0), bym = BLUR_AT(-1, 0), bc = BLUR_AT(0, 0);
    float bxp = BLUR_AT(0, 1), bxm = BLUR_AT(0, -1);
#undef BLUR_AT
    float gyv = (i == 0) ? (byp - bc) : (i == H-1) ? (bc - bym) : 0.5f * (byp - bym);
    float gxv = (j == 0) ? (bxp - bc) : (j == W-1) ? (bc - bxm) : 0.5f * (bxp - bxm);
    float r = sqrtf(gxv*gxv + gyv*gyv);
    if (r > 0.f) { cs = gxv / r; ss = gyv / r; }
    else         { cs = 1.f;     ss = 0.f;     }   // atan2(0,0)=0
}

// ---------------- K1: fused sparsify + correspondence search + tile binning ----------------
#define STY 8
#define STX 32
__global__ void __launch_bounds__(STY*STX) k_seed(const float* __restrict__ src,
                                                  const float* __restrict__ dst,
                                                  const int* __restrict__ xx,
                                                  const int* __restrict__ yy, int K) {
    __shared__ int s_pos[48];
    __shared__ int s_cnt;

    int b = blockIdx.z;
    int gy0 = blockIdx.y * STY, gx0 = blockIdx.x * STX;
    int tid = threadIdx.y * STX + threadIdx.x;
    const float* S = src + b*NPIX;
    const float* D = dst + b*NPIX;

    if (tid == 0) s_cnt = 0;
    __syncthreads();

    // phase 1: keep-test (min linear index edge in 5x5 window)
    int i = gy0 + threadIdx.y, j = gx0 + threadIdx.x;
    int p = i*W + j;
    if (S[p] > 0.5f) {
        bool kept = true;
#pragma unroll
        for (int a = -2; a <= 2; a++) {
            int ii = i + a;
            if (ii < 0 || ii >= H) continue;
#pragma unroll
            for (int c = -2; c <= 2; c++) {
                int jj = j + c;
                if (jj < 0 || jj >= W) continue;
                int q = ii*W + jj;
                if (q < p && S[q] > 0.5f) kept = false;
            }
        }
        if (kept) { int idx = atomicAdd(&s_cnt, 1); s_pos[idx] = p; }
    }
    __syncthreads();
    int n = s_cnt;

    // phase 2: warp per kept point, 105 offsets over lanes
    int warp = tid >> 5, lane = tid & 31;
    for (int pt = warp; pt < n; pt += STY*STX/32) {
        int pp = s_pos[pt];
        int pi = pp / W, pj = pp - (pp / W) * W;
        float cs, ssv;
        orient(S, pi, pj, cs, ssv);   // uniform addresses across warp -> broadcast loads
        float best = 1e9f; int bk = 0x7fffffff;
        for (int k = lane; k < K; k += 32) {
            int ox = xx[k], oy = yy[k];
            int ii = pi + oy, jj = pj + ox;
            if (ii >= 0 && ii < H && jj >= 0 && jj < W) {
                int q = ii*W + jj;
                if (D[q] > 0.5f) {
                    float cd, sd;
                    orient(D, ii, jj, cd, sd);   // rare (~2 hits/point)
                    float ang = 1.0f - (cs*cd + ssv*sd);
                    float sc = 20.0f * sqrtf((float)(ox*ox + oy*oy)) + 10.5f * ang;
                    if (sc < best) { best = sc; bk = k; }
                }
            }
        }
        // warp lexicographic (score, k) min -> global first-index-of-min (argmin semantics)
#pragma unroll
        for (int o = 16; o; o >>= 1) {
            float s2 = __shfl_xor_sync(0xffffffffu, best, o);
            int   k2 = __shfl_xor_sync(0xffffffffu, bk, o);
            if (s2 < best || (s2 == best && k2 < bk)) { best = s2; bk = k2; }
        }
        if (lane == 0 && best < 5e8f) {
            float2 dxy = make_float2((float)xx[bk], (float)yy[bk]);
            int pos = (pi << 16) | pj;
            // bin into every 32x32 output tile whose 52x52 halo contains (pi,pj):
            // tile origin ty0 in [pi-41, pi+10], tx0 in [pj-41, pj+10]  -> <=2 per axis
            int tylo = (pi <= 41) ? 0 : ((pi - 41 + 31) >> 5);
            int tyhi = min(TY_N - 1, (pi + 10) >> 5);
            int txlo = (pj <= 41) ? 0 : ((pj - 41 + 31) >> 5);
            int txhi = min(TX_N - 1, (pj + 10) >> 5);
            for (int ty = tylo; ty <= tyhi; ty++)
                for (int tx = txlo; tx <= txhi; tx++) {
                    int tile = (b * TY_N + ty) * TX_N + tx;
                    int idx = atomicAdd(&g_tcnt[tile], 1);
                    if (idx < TCAP) {
                        g_tpos[tile*TCAP + idx] = pos;
                        g_tdxy[tile*TCAP + idx] = dxy;
                    }
                }
        }
    }
}

// ---------------- K2: sparse diffusion over 21x21 sense window + final output ----------------
__global__ void __launch_bounds__(TS*TS) k_diffuse(float* __restrict__ out) {
    __shared__ float  s_wk[441];
    __shared__ int    s_pos[TCAP];
    __shared__ float2 s_dxy[TCAP];

    int bb  = blockIdx.z;
    int tid = threadIdx.y * TS + threadIdx.x;
    int tile = (bb * TY_N + blockIdx.y) * TX_N + blockIdx.x;

    if (tid < 441) {
        int dy = tid / 21 - 10, dx = tid % 21 - 10;
        s_wk[tid] = expf(-sqrtf((float)(dx*dx + dy*dy)) / 5.0f);
    }
    int m = min(g_tcnt[tile], TCAP);
    if (tid < m) {
        s_pos[tid] = g_tpos[tile*TCAP + tid];
        s_dxy[tid] = g_tdxy[tile*TCAP + tid];
    }
    __syncthreads();

    int oy = blockIdx.y * TS + threadIdx.y;
    int ox = blockIdx.x * TS + threadIdx.x;

    float nx = 0.f, ny = 0.f, den = 0.f;
    for (int pI = 0; pI < m; pI++) {
        int pos = s_pos[pI];
        int ddy = (pos >> 16) - oy + HALO;
        int ddx = (pos & 0xffff) - ox + HALO;
        if ((unsigned)ddy <= 2*HALO && (unsigned)ddx <= 2*HALO) {
            float w = s_wk[ddy * 21 + ddx];
            float2 d = s_dxy[pI];
            nx += w * d.x;
            ny += w * d.y;
            den += w;
        }
    }
    float inv = 1.0f / (den + 1e-6f);
    int q = oy*W + ox;
    out[(bb*2 + 0)*NPIX + q] = (float)ox + 0.6f * nx * inv;
    out[(bb*2 + 1)*NPIX + q] = (float)oy + 0.6f * ny * inv;
}

extern "C" void kernel_launch(void* const* d_in, const int* in_sizes, int n_in,
                              void* d_out, int out_size) {
    const float* src = (const float*)d_in[0];
    const float* dst = (const float*)d_in[1];
    const int*   xx  = (const int*)d_in[2];
    const int*   yy  = (const int*)d_in[3];
    int K = in_sizes[2];
    float* out = (float*)d_out;

    void* cntp = nullptr;
    cudaGetSymbolAddress(&cntp, g_tcnt);
    cudaMemsetAsync(cntp, 0, BB * NTILE * sizeof(int));

    dim3 gs(W/STX, H/STY, BB), ts(STX, STY);
    k_seed<<<gs, ts>>>(src, dst, xx, yy, K);

    dim3 gd(TX_N, TY_N, BB), td(TS, TS);
    k_diffuse<<<gd, td>>>(out);
}